// round 9
// baseline (speedup 1.0000x reference)
#include <cuda_runtime.h>
#include <cstdint>

#define DIMIN 64
#define HID   170
#define C2    340
#define BATCH 4
#define HW    256

typedef unsigned long long f32x2_t;   // packed pair of fp32

// Intermediate buffer t = FFT-filtered projection, [4,340,256,256] fp32 (356MB scratch)
__device__ float g_t[(size_t)BATCH * C2 * HW * HW];
// Pre-transposed project_out weights (built by kPrep each launch)
__device__ float g_WoT[HID * DIMIN];   // [hc][o]

// ---------- packed f32x2 helpers ----------
__device__ __forceinline__ f32x2_t ffma2(f32x2_t a, f32x2_t b, f32x2_t c) {
    f32x2_t d;
    asm("fma.rn.f32x2 %0, %1, %2, %3;" : "=l"(d) : "l"(a), "l"(b), "l"(c));
    return d;
}
__device__ __forceinline__ f32x2_t dup2(float v) {
    f32x2_t d;
    asm("mov.b64 %0, {%1, %1};" : "=l"(d) : "f"(v));
    return d;
}
__device__ __forceinline__ void unpack2(f32x2_t v, float& lo, float& hi) {
    asm("mov.b64 {%0, %1}, %2;" : "=f"(lo), "=f"(hi) : "l"(v));
}

// ---------- unrolled 8-point complex FFT (sgn=-1 fwd, +1 inv, unnormalized) ----------
__device__ __forceinline__ void fft8(float* xr, float* xi, float sgn) {
    float tr, ti;
    tr = xr[1]; xr[1] = xr[4]; xr[4] = tr;  ti = xi[1]; xi[1] = xi[4]; xi[4] = ti;
    tr = xr[3]; xr[3] = xr[6]; xr[6] = tr;  ti = xi[3]; xi[3] = xi[6]; xi[6] = ti;
    #pragma unroll
    for (int i = 0; i < 8; i += 2) {
        float ar = xr[i], ai = xi[i], br = xr[i+1], bi = xi[i+1];
        xr[i] = ar + br; xi[i] = ai + bi; xr[i+1] = ar - br; xi[i+1] = ai - bi;
    }
    #pragma unroll
    for (int i = 0; i < 8; i += 4) {
        { float ar = xr[i], ai = xi[i], br = xr[i+2], bi = xi[i+2];
          xr[i] = ar + br; xi[i] = ai + bi; xr[i+2] = ar - br; xi[i+2] = ai - bi; }
        { float ar = xr[i+1], ai = xi[i+1], br = xr[i+3], bi = xi[i+3];
          float wr = -sgn * bi, wi = sgn * br;
          xr[i+1] = ar + wr; xi[i+1] = ai + wi; xr[i+3] = ar - wr; xi[i+3] = ai - wi; }
    }
    const float c = 0.70710678118654752f;
    { float ar = xr[0], ai = xi[0], br = xr[4], bi = xi[4];
      xr[0] = ar + br; xi[0] = ai + bi; xr[4] = ar - br; xi[4] = ai - bi; }
    { float ar = xr[1], ai = xi[1], br = xr[5], bi = xi[5];
      float wr = c * (br - sgn * bi), wi = c * (bi + sgn * br);
      xr[1] = ar + wr; xi[1] = ai + wi; xr[5] = ar - wr; xi[5] = ai - wi; }
    { float ar = xr[2], ai = xi[2], br = xr[6], bi = xi[6];
      float wr = -sgn * bi, wi = sgn * br;
      xr[2] = ar + wr; xi[2] = ai + wi; xr[6] = ar - wr; xi[6] = ai - wi; }
    { float ar = xr[3], ai = xi[3], br = xr[7], bi = xi[7];
      float wr = c * (-br - sgn * bi), wi = c * (-bi + sgn * br);
      xr[3] = ar + wr; xi[3] = ai + wi; xr[7] = ar - wr; xi[7] = ai - wi; }
}

__device__ __forceinline__ void fft_filter_store(int oc, const f32x2_t* acc,
                                                 const float* __restrict__ filt,
                                                 int b, int ph, int pw) {
    float a[64];
    #pragma unroll
    for (int j = 0; j < 32; j++) unpack2(acc[j], a[2*j], a[2*j+1]);

    float re[8][5], im[8][5];
    #pragma unroll
    for (int r = 0; r < 8; r++) {
        float xr[8], xi[8];
        #pragma unroll
        for (int c = 0; c < 8; c++) { xr[c] = a[r*8 + c]; xi[c] = 0.f; }
        fft8(xr, xi, -1.f);
        #pragma unroll
        for (int k = 0; k < 5; k++) { re[r][k] = xr[k]; im[r][k] = xi[k]; }
    }
    const float* fch = filt + oc * 40;
    #pragma unroll
    for (int k = 0; k < 5; k++) {
        float xr[8], xi[8];
        #pragma unroll
        for (int r = 0; r < 8; r++) { xr[r] = re[r][k]; xi[r] = im[r][k]; }
        fft8(xr, xi, -1.f);
        #pragma unroll
        for (int r = 0; r < 8; r++) {
            float f = __ldg(fch + r*5 + k) * (1.f / 64.f);
            xr[r] *= f; xi[r] *= f;
        }
        fft8(xr, xi, 1.f);
        #pragma unroll
        for (int r = 0; r < 8; r++) { re[r][k] = xr[r]; im[r][k] = xi[r]; }
    }
    float* ob = g_t + (((size_t)(b * C2 + oc) * HW + ph*8) * HW + pw*8);
    #pragma unroll
    for (int r = 0; r < 8; r++) {
        float xr[8], xi[8];
        #pragma unroll
        for (int k = 0; k < 5; k++) { xr[k] = re[r][k]; xi[k] = im[r][k]; }
        xr[5] = re[r][3]; xi[5] = -im[r][3];
        xr[6] = re[r][2]; xi[6] = -im[r][2];
        xr[7] = re[r][1]; xi[7] = -im[r][1];
        fft8(xr, xi, 1.f);
        float4 v0 = make_float4(xr[0], xr[1], xr[2], xr[3]);
        float4 v1 = make_float4(xr[4], xr[5], xr[6], xr[7]);
        *(float4*)(ob + (size_t)r * HW)     = v0;
        *(float4*)(ob + (size_t)r * HW + 4) = v1;
    }
}

// ================= Prep: transpose project_out weights once per launch =================
__global__ void kPrep(const float* __restrict__ Wout) {
    int i = blockIdx.x * 256 + threadIdx.x;
    if (i < DIMIN * HID) {
        int o = i / HID, hc = i % HID;
        g_WoT[hc * DIMIN + o] = Wout[i];
    }
}

// ================= Kernel A: project_in (64->340) + patch FFT filter =================
// (identical to the measured R4 version: smem-staged weights)
#define KA_THREADS 176
#define SMEM_A (64*64*4 + C2*DIMIN*4)   // patch (16KB) + transposed W_in (87KB)

__global__ void __launch_bounds__(KA_THREADS, 2)
kA(const float* __restrict__ x, const float* __restrict__ Win,
   const float* __restrict__ filt) {
    extern __shared__ float sm[];
    float* sX = sm;             // [ic][64 pix]
    float* sW = sm + 64 * 64;   // transposed: [ic][oc]

    const int t  = threadIdx.x;
    const int pw = blockIdx.x, ph = blockIdx.y, b = blockIdx.z;

    for (int i = t; i < 1024; i += KA_THREADS) {
        int ic = i >> 4, rr = (i >> 1) & 7, half = i & 1;
        float4 v = *(const float4*)(x + (((size_t)(b * DIMIN + ic) * HW + ph*8 + rr) * HW + pw*8 + half*4));
        *(float4*)(sX + ic*64 + rr*8 + half*4) = v;
    }
    for (int i = t; i < C2 * DIMIN; i += KA_THREADS) {
        int oc = i >> 6, ic = i & 63;
        sW[ic * C2 + oc] = Win[i];
    }
    __syncthreads();

    const int oc0 = t;
    const int oc1 = t + KA_THREADS;
    const bool has1 = (oc1 < C2);
    const int oc1c = has1 ? oc1 : 0;

    f32x2_t a0[32], a1[32];
    #pragma unroll
    for (int j = 0; j < 32; j++) { a0[j] = 0ull; a1[j] = 0ull; }

    const ulonglong2* sX4 = (const ulonglong2*)sX;
    #pragma unroll 2
    for (int ic = 0; ic < 64; ic++) {
        f32x2_t w0 = dup2(sW[ic * C2 + oc0]);
        f32x2_t w1 = dup2(sW[ic * C2 + oc1c]);
        #pragma unroll
        for (int j = 0; j < 16; j++) {
            ulonglong2 xv = sX4[ic * 16 + j];
            a0[2*j]   = ffma2(w0, xv.x, a0[2*j]);
            a0[2*j+1] = ffma2(w0, xv.y, a0[2*j+1]);
            a1[2*j]   = ffma2(w1, xv.x, a1[2*j]);
            a1[2*j+1] = ffma2(w1, xv.y, a1[2*j+1]);
        }
    }
    __syncthreads();

    f32x2_t* sSpill = (f32x2_t*)sm;   // [32][KA_THREADS]
    #pragma unroll
    for (int j = 0; j < 32; j++) sSpill[j * KA_THREADS + t] = a1[j];

    fft_filter_store(oc0, a0, filt, b, ph, pw);

    if (has1) {
        f32x2_t a1b[32];
        #pragma unroll
        for (int j = 0; j < 32; j++) a1b[j] = sSpill[j * KA_THREADS + t];
        fft_filter_store(oc1, a1b, filt, b, ph, pw);
    }
}

// ============ Kernel B: depthwise 3x3 + GELU gate + project_out (170->64) ============
// grid (16,16,4), 256 threads, 16x16 tile, 17 chunks of 10 channel-pairs.
// Phase B: task = (pair,col,rowgroup) computes 4 stacked pixels by ROW STREAMING
// (3-value sliding rows into 4 accumulators — no 6x3 register tile, no spills).
// Phase C: register-tiled 256px x 64out x 10k GEMM; weights via uniform __ldg.
#define SDW_F   (C2 * 12)                         // padded dw weights (stride 12)
#define ST_F    (20 * 18 * 20)                    // 20 ch x 18 rows x stride-20
#define SG_F    (10 * 256)
#define SMEM_B  ((SDW_F + ST_F + SG_F) * 4)       // 55360 bytes

__device__ __forceinline__ void dw3x3_rows4(const float* __restrict__ tp,
                                            const float4 w0, const float4 w1,
                                            const float w8, float* d) {
    d[0] = d[1] = d[2] = d[3] = 0.f;
    #pragma unroll
    for (int r = 0; r < 6; r++) {
        float x0 = tp[r*20 + 0], x1 = tp[r*20 + 1], x2 = tp[r*20 + 2];
        if (r <= 3)           d[r]   = fmaf(x0, w0.x, fmaf(x1, w0.y, fmaf(x2, w0.z, d[r])));
        if (r >= 1 && r <= 4) d[r-1] = fmaf(x0, w0.w, fmaf(x1, w1.x, fmaf(x2, w1.y, d[r-1])));
        if (r >= 2)           d[r-2] = fmaf(x0, w1.z, fmaf(x1, w1.w, fmaf(x2, w8,  d[r-2])));
    }
}

__global__ void __launch_bounds__(256, 2)
kB(const float* __restrict__ Wdw, float* __restrict__ out) {
    extern __shared__ float sm[];
    float* sDw = sm;                  // [340][12] (9 used)
    float* sT  = sm + SDW_F;          // [20][18][20]
    float* sG  = sm + SDW_F + ST_F;   // [10][256]

    const int t  = threadIdx.x;
    const int bx = blockIdx.x * 16, by = blockIdx.y * 16, b = blockIdx.z;

    // GEMM-phase mapping: warp = 8 outputs, lane = 8 pixels
    const int outg = t >> 5;
    const int p0   = (t & 31) * 8;

    // halo mapping (fixed per thread): slot1 = t, slot2 = t + 256 (t < 68)
    const int ly1 = t / 18, lx1 = t % 18;
    const int ly2 = (t + 256) / 18, lx2 = (t + 256) % 18;
    const bool ok1 = (by - 1 + ly1 >= 0) && (by - 1 + ly1 < HW) &&
                     (bx - 1 + lx1 >= 0) && (bx - 1 + lx1 < HW);
    const bool ok2 = (t < 68) && (by - 1 + ly2 >= 0) && (by - 1 + ly2 < HW) &&
                     (bx - 1 + lx2 >= 0) && (bx - 1 + lx2 < HW);
    const int off1 = (by - 1 + ly1) * HW + (bx - 1 + lx1);
    const int off2 = (by - 1 + ly2) * HW + (bx - 1 + lx2);
    const int s1 = ly1 * 20 + lx1;
    const int s2 = ly2 * 20 + lx2;
    const float* gbase = g_t + (size_t)b * C2 * (HW * HW);

    for (int i = t; i < C2 * 9; i += 256) {
        int ch = i / 9, j = i % 9;
        sDw[ch * 12 + j] = Wdw[i];
    }

    f32x2_t acc[8][4];
    #pragma unroll
    for (int o = 0; o < 8; o++)
        #pragma unroll
        for (int pp = 0; pp < 4; pp++) acc[o][pp] = 0ull;

    for (int cc = 0; cc < 17; cc++) {
        // ---- halo load: 20 channels x 18x18 (stride 20), zero padded ----
        #pragma unroll 4
        for (int ch = 0; ch < 20; ch++) {
            int chg = (ch < 10) ? (cc * 10 + ch) : (HID + cc * 10 + (ch - 10));
            const float* cptr = gbase + (size_t)chg * (HW * HW);
            sT[ch * 360 + s1] = ok1 ? cptr[off1] : 0.f;
            if (t < 68) sT[ch * 360 + s2] = ok2 ? cptr[off2] : 0.f;
        }
        __syncthreads();   // halo + sDw ready; prev phase C done with sG

        // ---- phase B: 640 tasks = 10 pairs x 16 cols x 4 rowgroups ----
        #pragma unroll
        for (int it = 0; it < 3; it++) {
            int tau = t + it * 256;
            if (tau < 640) {
                int pair = tau >> 6;
                int col  = tau & 15;
                int rg   = (tau >> 4) & 3;
                int hc   = cc * 10 + pair;
                const float* ta = sT + pair * 360 + rg * 80 + col;

                float da[4], db[4];
                {
                    const float* wp = sDw + hc * 12;
                    float4 w0 = *(const float4*)wp;
                    float4 w1 = *(const float4*)(wp + 4);
                    dw3x3_rows4(ta, w0, w1, wp[8], da);
                }
                {
                    const float* wp = sDw + (hc + HID) * 12;
                    float4 w0 = *(const float4*)wp;
                    float4 w1 = *(const float4*)(wp + 4);
                    dw3x3_rows4(ta + 10 * 360, w0, w1, wp[8], db);
                }
                #pragma unroll
                for (int i = 0; i < 4; i++) {
                    float g = 0.5f * da[i] * (1.f + erff(da[i] * 0.70710678118654752f)) * db[i];
                    sG[pair * 256 + (rg * 4 + i) * 16 + col] = g;
                }
            }
        }
        __syncthreads();   // sG ready; all phase-B reads of sT done

        // ---- phase C: projection GEMM update (k = 10) ----
        #pragma unroll
        for (int c = 0; c < 10; c++) {
            int hc = cc * 10 + c;
            const ulonglong2* gp = (const ulonglong2*)(sG + c * 256 + p0);
            ulonglong2 gv0 = gp[0], gv1 = gp[1];
            const float4* wp = (const float4*)(g_WoT + hc * 64 + outg * 8);
            float4 w0 = __ldg(wp), w1 = __ldg(wp + 1);
            f32x2_t wd[8];
            wd[0] = dup2(w0.x); wd[1] = dup2(w0.y); wd[2] = dup2(w0.z); wd[3] = dup2(w0.w);
            wd[4] = dup2(w1.x); wd[5] = dup2(w1.y); wd[6] = dup2(w1.z); wd[7] = dup2(w1.w);
            #pragma unroll
            for (int o = 0; o < 8; o++) {
                acc[o][0] = ffma2(wd[o], gv0.x, acc[o][0]);
                acc[o][1] = ffma2(wd[o], gv0.y, acc[o][1]);
                acc[o][2] = ffma2(wd[o], gv1.x, acc[o][2]);
                acc[o][3] = ffma2(wd[o], gv1.y, acc[o][3]);
            }
        }
        // safe: next halo writes sT only, and everyone passes the post-halo
        // __syncthreads before touching sG again.
    }

    const int py  = p0 >> 4;
    const int px0 = p0 & 15;
    #pragma unroll
    for (int o = 0; o < 8; o++) {
        int oc = outg * 8 + o;
        float v[8];
        #pragma unroll
        for (int pp = 0; pp < 4; pp++) unpack2(acc[o][pp], v[2*pp], v[2*pp+1]);
        float* ob = out + (((size_t)(b * DIMIN + oc)) * HW + (by + py)) * HW + (bx + px0);
        *(float4*)(ob)     = make_float4(v[0], v[1], v[2], v[3]);
        *(float4*)(ob + 4) = make_float4(v[4], v[5], v[6], v[7]);
    }
}

// ======================== launch ========================
extern "C" void kernel_launch(void* const* d_in, const int* in_sizes, int n_in,
                              void* d_out, int out_size) {
    (void)in_sizes; (void)n_in; (void)out_size;
    const float* x    = (const float*)d_in[0];
    const float* Win  = (const float*)d_in[1];
    const float* Wdw  = (const float*)d_in[2];
    const float* filt = (const float*)d_in[3];
    const float* Wout = (const float*)d_in[4];
    float* out = (float*)d_out;

    cudaFuncSetAttribute(kA, cudaFuncAttributeMaxDynamicSharedMemorySize, SMEM_A);
    cudaFuncSetAttribute(kB, cudaFuncAttributeMaxDynamicSharedMemorySize, SMEM_B);

    kPrep<<<(DIMIN * HID + 255) / 256, 256>>>(Wout);
    kA<<<dim3(32, 32, BATCH), KA_THREADS, SMEM_A>>>(x, Win, filt);
    kB<<<dim3(16, 16, BATCH), 256, SMEM_B>>>(Wdw, out);
}

// round 10
// speedup vs baseline: 1.4798x; 1.4798x over previous
#include <cuda_runtime.h>
#include <cstdint>

#define DIMIN 64
#define HID   170
#define C2    340
#define BATCH 4
#define HW    256

typedef unsigned long long f32x2_t;   // packed pair of fp32

// Intermediate buffer t = FFT-filtered projection, [4,340,256,256] fp32 (356MB scratch)
__device__ float g_t[(size_t)BATCH * C2 * HW * HW];

// ---------- packed f32x2 helpers ----------
__device__ __forceinline__ f32x2_t ffma2(f32x2_t a, f32x2_t b, f32x2_t c) {
    f32x2_t d;
    asm("fma.rn.f32x2 %0, %1, %2, %3;" : "=l"(d) : "l"(a), "l"(b), "l"(c));
    return d;
}
__device__ __forceinline__ f32x2_t dup2(float v) {
    f32x2_t d;
    asm("mov.b64 %0, {%1, %1};" : "=l"(d) : "f"(v));
    return d;
}
__device__ __forceinline__ void unpack2(f32x2_t v, float& lo, float& hi) {
    asm("mov.b64 {%0, %1}, %2;" : "=f"(lo), "=f"(hi) : "l"(v));
}

// ---------- unrolled 8-point complex FFT (sgn=-1 fwd, +1 inv, unnormalized) ----------
__device__ __forceinline__ void fft8(float* xr, float* xi, float sgn) {
    float tr, ti;
    tr = xr[1]; xr[1] = xr[4]; xr[4] = tr;  ti = xi[1]; xi[1] = xi[4]; xi[4] = ti;
    tr = xr[3]; xr[3] = xr[6]; xr[6] = tr;  ti = xi[3]; xi[3] = xi[6]; xi[6] = ti;
    #pragma unroll
    for (int i = 0; i < 8; i += 2) {
        float ar = xr[i], ai = xi[i], br = xr[i+1], bi = xi[i+1];
        xr[i] = ar + br; xi[i] = ai + bi; xr[i+1] = ar - br; xi[i+1] = ai - bi;
    }
    #pragma unroll
    for (int i = 0; i < 8; i += 4) {
        { float ar = xr[i], ai = xi[i], br = xr[i+2], bi = xi[i+2];
          xr[i] = ar + br; xi[i] = ai + bi; xr[i+2] = ar - br; xi[i+2] = ai - bi; }
        { float ar = xr[i+1], ai = xi[i+1], br = xr[i+3], bi = xi[i+3];
          float wr = -sgn * bi, wi = sgn * br;
          xr[i+1] = ar + wr; xi[i+1] = ai + wi; xr[i+3] = ar - wr; xi[i+3] = ai - wi; }
    }
    const float c = 0.70710678118654752f;
    { float ar = xr[0], ai = xi[0], br = xr[4], bi = xi[4];
      xr[0] = ar + br; xi[0] = ai + bi; xr[4] = ar - br; xi[4] = ai - bi; }
    { float ar = xr[1], ai = xi[1], br = xr[5], bi = xi[5];
      float wr = c * (br - sgn * bi), wi = c * (bi + sgn * br);
      xr[1] = ar + wr; xi[1] = ai + wi; xr[5] = ar - wr; xi[5] = ai - wi; }
    { float ar = xr[2], ai = xi[2], br = xr[6], bi = xi[6];
      float wr = -sgn * bi, wi = sgn * br;
      xr[2] = ar + wr; xi[2] = ai + wi; xr[6] = ar - wr; xi[6] = ai - wi; }
    { float ar = xr[3], ai = xi[3], br = xr[7], bi = xi[7];
      float wr = c * (-br - sgn * bi), wi = c * (-bi + sgn * br);
      xr[3] = ar + wr; xi[3] = ai + wi; xr[7] = ar - wr; xi[7] = ai - wi; }
}

__device__ __forceinline__ void fft_filter_store(int oc, const f32x2_t* acc,
                                                 const float* __restrict__ filt,
                                                 int b, int ph, int pw) {
    float a[64];
    #pragma unroll
    for (int j = 0; j < 32; j++) unpack2(acc[j], a[2*j], a[2*j+1]);

    float re[8][5], im[8][5];
    #pragma unroll
    for (int r = 0; r < 8; r++) {
        float xr[8], xi[8];
        #pragma unroll
        for (int c = 0; c < 8; c++) { xr[c] = a[r*8 + c]; xi[c] = 0.f; }
        fft8(xr, xi, -1.f);
        #pragma unroll
        for (int k = 0; k < 5; k++) { re[r][k] = xr[k]; im[r][k] = xi[k]; }
    }
    const float* fch = filt + oc * 40;
    #pragma unroll
    for (int k = 0; k < 5; k++) {
        float xr[8], xi[8];
        #pragma unroll
        for (int r = 0; r < 8; r++) { xr[r] = re[r][k]; xi[r] = im[r][k]; }
        fft8(xr, xi, -1.f);
        #pragma unroll
        for (int r = 0; r < 8; r++) {
            float f = __ldg(fch + r*5 + k) * (1.f / 64.f);
            xr[r] *= f; xi[r] *= f;
        }
        fft8(xr, xi, 1.f);
        #pragma unroll
        for (int r = 0; r < 8; r++) { re[r][k] = xr[r]; im[r][k] = xi[r]; }
    }
    float* ob = g_t + (((size_t)(b * C2 + oc) * HW + ph*8) * HW + pw*8);
    #pragma unroll
    for (int r = 0; r < 8; r++) {
        float xr[8], xi[8];
        #pragma unroll
        for (int k = 0; k < 5; k++) { xr[k] = re[r][k]; xi[k] = im[r][k]; }
        xr[5] = re[r][3]; xi[5] = -im[r][3];
        xr[6] = re[r][2]; xi[6] = -im[r][2];
        xr[7] = re[r][1]; xi[7] = -im[r][1];
        fft8(xr, xi, 1.f);
        float4 v0 = make_float4(xr[0], xr[1], xr[2], xr[3]);
        float4 v1 = make_float4(xr[4], xr[5], xr[6], xr[7]);
        *(float4*)(ob + (size_t)r * HW)     = v0;
        *(float4*)(ob + (size_t)r * HW + 4) = v1;
    }
}

// ================= Kernel A: project_in (64->340) + patch FFT filter =================
// (identical to the measured R4 version)
#define KA_THREADS 176
#define SMEM_A (64*64*4 + C2*DIMIN*4)   // patch (16KB) + transposed W_in (87KB)

__global__ void __launch_bounds__(KA_THREADS, 2)
kA(const float* __restrict__ x, const float* __restrict__ Win,
   const float* __restrict__ filt) {
    extern __shared__ float sm[];
    float* sX = sm;             // [ic][64 pix]
    float* sW = sm + 64 * 64;   // transposed: [ic][oc]

    const int t  = threadIdx.x;
    const int pw = blockIdx.x, ph = blockIdx.y, b = blockIdx.z;

    for (int i = t; i < 1024; i += KA_THREADS) {
        int ic = i >> 4, rr = (i >> 1) & 7, half = i & 1;
        float4 v = *(const float4*)(x + (((size_t)(b * DIMIN + ic) * HW + ph*8 + rr) * HW + pw*8 + half*4));
        *(float4*)(sX + ic*64 + rr*8 + half*4) = v;
    }
    for (int i = t; i < C2 * DIMIN; i += KA_THREADS) {
        int oc = i >> 6, ic = i & 63;
        sW[ic * C2 + oc] = Win[i];
    }
    __syncthreads();

    const int oc0 = t;
    const int oc1 = t + KA_THREADS;
    const bool has1 = (oc1 < C2);
    const int oc1c = has1 ? oc1 : 0;

    f32x2_t a0[32], a1[32];
    #pragma unroll
    for (int j = 0; j < 32; j++) { a0[j] = 0ull; a1[j] = 0ull; }

    const ulonglong2* sX4 = (const ulonglong2*)sX;
    #pragma unroll 2
    for (int ic = 0; ic < 64; ic++) {
        f32x2_t w0 = dup2(sW[ic * C2 + oc0]);
        f32x2_t w1 = dup2(sW[ic * C2 + oc1c]);
        #pragma unroll
        for (int j = 0; j < 16; j++) {
            ulonglong2 xv = sX4[ic * 16 + j];
            a0[2*j]   = ffma2(w0, xv.x, a0[2*j]);
            a0[2*j+1] = ffma2(w0, xv.y, a0[2*j+1]);
            a1[2*j]   = ffma2(w1, xv.x, a1[2*j]);
            a1[2*j+1] = ffma2(w1, xv.y, a1[2*j+1]);
        }
    }
    __syncthreads();

    f32x2_t* sSpill = (f32x2_t*)sm;   // [32][KA_THREADS]
    #pragma unroll
    for (int j = 0; j < 32; j++) sSpill[j * KA_THREADS + t] = a1[j];

    fft_filter_store(oc0, a0, filt, b, ph, pw);

    if (has1) {
        f32x2_t a1b[32];
        #pragma unroll
        for (int j = 0; j < 32; j++) a1b[j] = sSpill[j * KA_THREADS + t];
        fft_filter_store(oc1, a1b, filt, b, ph, pw);
    }
}

// ============ Kernel B: depthwise 3x3 + GELU gate + project_out (170->64) ============
// R4 structure exactly, with ONE change: sDw padded to stride 12 so each 9-weight
// filter loads as 2x LDS.128 + 1x LDS.32 (6 loads) instead of 18 scalar LDS.
#define SWO_F   (HID * 64)
#define SDW_F   (C2 * 12)
#define ST_F    (20 * 324)
#define SG_F    (10 * 256)
#define SMEM_B  ((SWO_F + SDW_F + ST_F + SG_F) * 4)   // 96000 bytes

__global__ void __launch_bounds__(256, 2)
kB(const float* __restrict__ Wdw, const float* __restrict__ Wout,
   float* __restrict__ out) {
    extern __shared__ float sm[];
    float* sWo = sm;                          // transposed: [hc][64 o]
    float* sDw = sm + SWO_F;                  // [340][12] (9 used)
    float* sT  = sm + SWO_F + SDW_F;          // [20][18*18]
    float* sG  = sm + SWO_F + SDW_F + ST_F;   // [10][256]

    const int t  = threadIdx.x;
    const int tx = t & 15, ty = t >> 4;
    const int bx = blockIdx.x * 16, by = blockIdx.y * 16, b = blockIdx.z;

    // GEMM-phase thread mapping: warp = output group of 8, lane = pixel group of 8
    const int outg = t >> 5;
    const int p0   = (t & 31) * 8;

    for (int i = t; i < DIMIN * HID; i += 256) {
        int o = i / HID, hc = i % HID;
        sWo[hc * 64 + o] = Wout[i];
    }
    for (int i = t; i < C2 * 9; i += 256) {
        int ch = i / 9, j = i % 9;
        sDw[ch * 12 + j] = Wdw[i];
    }

    f32x2_t acc[8][4];
    #pragma unroll
    for (int o = 0; o < 8; o++)
        #pragma unroll
        for (int pp = 0; pp < 4; pp++) acc[o][pp] = 0ull;

    for (int cc = 0; cc < 17; cc++) {
        __syncthreads();  // sT safe to overwrite; first iter: orders sWo/sDw
        // halo tile load: 20 channels (10 gate-a + 10 gate-b) x 18x18, zero padded
        for (int i = t; i < 20 * 324; i += 256) {
            int s = i / 324, p = i % 324;
            int ly = p / 18, lx = p % 18;
            int ch = (s < 10) ? (cc * 10 + s) : (HID + cc * 10 + (s - 10));
            int gy = by - 1 + ly, gx = bx - 1 + lx;
            float v = 0.f;
            if (gy >= 0 && gy < HW && gx >= 0 && gx < HW)
                v = g_t[(((size_t)b * C2 + ch) * HW + gy) * HW + gx];
            sT[i] = v;
        }
        __syncthreads();

        // -------- phase B: dw conv + exact GELU gate, stage g to sG --------
        #pragma unroll 2
        for (int c = 0; c < 10; c++) {
            int hc = cc * 10 + c;
            // weights: 2x LDS.128 + 1 scalar per filter (broadcast)
            const float* wp1 = sDw + hc * 12;
            const float* wp2 = sDw + (hc + HID) * 12;
            float4 w1a = *(const float4*)wp1;
            float4 w1b = *(const float4*)(wp1 + 4);
            float  w1c = wp1[8];
            float4 w2a = *(const float4*)wp2;
            float4 w2b = *(const float4*)(wp2 + 4);
            float  w2c = wp2[8];
            const float* t1 = sT + c * 324 + ty * 18 + tx;
            const float* t2 = t1 + 10 * 324;
            float d1, d2;
            d1 = t1[0]  * w1a.x; d2 = t2[0]  * w2a.x;
            d1 = fmaf(t1[1],  w1a.y, d1); d2 = fmaf(t2[1],  w2a.y, d2);
            d1 = fmaf(t1[2],  w1a.z, d1); d2 = fmaf(t2[2],  w2a.z, d2);
            d1 = fmaf(t1[18], w1a.w, d1); d2 = fmaf(t2[18], w2a.w, d2);
            d1 = fmaf(t1[19], w1b.x, d1); d2 = fmaf(t2[19], w2b.x, d2);
            d1 = fmaf(t1[20], w1b.y, d1); d2 = fmaf(t2[20], w2b.y, d2);
            d1 = fmaf(t1[36], w1b.z, d1); d2 = fmaf(t2[36], w2b.z, d2);
            d1 = fmaf(t1[37], w1b.w, d1); d2 = fmaf(t2[37], w2b.w, d2);
            d1 = fmaf(t1[38], w1c,   d1); d2 = fmaf(t2[38], w2c,   d2);
            float g = 0.5f * d1 * (1.f + erff(d1 * 0.70710678118654752f)) * d2;
            sG[c * 256 + t] = g;
        }
        __syncthreads();

        // -------- phase C: projection GEMM update (k = 10) --------
        #pragma unroll
        for (int c = 0; c < 10; c++) {
            int hc = cc * 10 + c;
            const ulonglong2* gp = (const ulonglong2*)(sG + c * 256 + p0);
            ulonglong2 gv0 = gp[0], gv1 = gp[1];
            const float4* wp = (const float4*)(sWo + hc * 64 + outg * 8);
            float4 w0 = wp[0], w1 = wp[1];
            f32x2_t wd[8];
            wd[0] = dup2(w0.x); wd[1] = dup2(w0.y); wd[2] = dup2(w0.z); wd[3] = dup2(w0.w);
            wd[4] = dup2(w1.x); wd[5] = dup2(w1.y); wd[6] = dup2(w1.z); wd[7] = dup2(w1.w);
            #pragma unroll
            for (int o = 0; o < 8; o++) {
                acc[o][0] = ffma2(wd[o], gv0.x, acc[o][0]);
                acc[o][1] = ffma2(wd[o], gv0.y, acc[o][1]);
                acc[o][2] = ffma2(wd[o], gv1.x, acc[o][2]);
                acc[o][3] = ffma2(wd[o], gv1.y, acc[o][3]);
            }
        }
    }

    // -------- store: thread owns outputs (outg*8..+7) x pixels (p0..p0+7) --------
    const int py  = p0 >> 4;
    const int px0 = p0 & 15;
    #pragma unroll
    for (int o = 0; o < 8; o++) {
        int oc = outg * 8 + o;
        float v[8];
        #pragma unroll
        for (int pp = 0; pp < 4; pp++) unpack2(acc[o][pp], v[2*pp], v[2*pp+1]);
        float* ob = out + (((size_t)(b * DIMIN + oc)) * HW + (by + py)) * HW + (bx + px0);
        *(float4*)(ob)     = make_float4(v[0], v[1], v[2], v[3]);
        *(float4*)(ob + 4) = make_float4(v[4], v[5], v[6], v[7]);
    }
}

// ======================== launch ========================
extern "C" void kernel_launch(void* const* d_in, const int* in_sizes, int n_in,
                              void* d_out, int out_size) {
    (void)in_sizes; (void)n_in; (void)out_size;
    const float* x    = (const float*)d_in[0];
    const float* Win  = (const float*)d_in[1];
    const float* Wdw  = (const float*)d_in[2];
    const float* filt = (const float*)d_in[3];
    const float* Wout = (const float*)d_in[4];
    float* out = (float*)d_out;

    cudaFuncSetAttribute(kA, cudaFuncAttributeMaxDynamicSharedMemorySize, SMEM_A);
    cudaFuncSetAttribute(kB, cudaFuncAttributeMaxDynamicSharedMemorySize, SMEM_B);

    kA<<<dim3(32, 32, BATCH), KA_THREADS, SMEM_A>>>(x, Win, filt);
    kB<<<dim3(16, 16, BATCH), 256, SMEM_B>>>(Wdw, Wout, out);
}